// round 1
// baseline (speedup 1.0000x reference)
#include <cuda_runtime.h>
#include <cstdint>
#include <cstddef>

// Problem dims
#define Bn 64
#define Tn 2048
#define Fn 256
#define Hn 512
#define On 128
#define NGROUP 16   // 16 groups x 4 batches
#define NSLICE 8    // 8 column slices of 64

// ---------------- workspaces (static device mem; no runtime alloc) -------------
__device__ float g_xp[(size_t)Bn * Tn * Hn];    // 256 MB: xp of current layer
__device__ float g_res[(size_t)Bn * Tn * Hn];   // 256 MB: layer-0 outputs
__device__ float g_hbuf[2][Bn * Hn];            // ping-pong hidden state
__device__ float g_hT[Bn * Hn];                 // final hidden of layer 1
__device__ unsigned int g_flags[NGROUP][NSLICE];

typedef unsigned long long u64t;

// ---------------- packed fp32x2 helpers (Blackwell) ----------------------------
__device__ __forceinline__ u64t fma2(u64t a, u64t b, u64t c) {
    u64t d;
    asm("fma.rn.f32x2 %0, %1, %2, %3;" : "=l"(d) : "l"(a), "l"(b), "l"(c));
    return d;
}
__device__ __forceinline__ u64t pk2(float lo, float hi) {
    u64t r;
    asm("mov.b64 %0, {%1, %2};" : "=l"(r) : "f"(lo), "f"(hi));
    return r;
}
__device__ __forceinline__ float2 upk(u64t v) {
    float2 f;
    asm("mov.b64 {%0, %1}, %2;" : "=f"(f.x), "=f"(f.y) : "l"(v));
    return f;
}

// ---------------- flag reset ----------------------------------------------------
__global__ void zero_flags_kernel() {
    if (threadIdx.x < NGROUP * NSLICE)
        ((unsigned int*)g_flags)[threadIdx.x] = 0u;
}

// ---------------- big GEMM: C[M,512] = A[M,K] * W[512,K]^T + b1 + b2 ------------
// BM=128, BN=128, BK=8, 256 threads, 8x8 microtile, f32x2 packed FMA.
template <bool FROM_RES>
__global__ __launch_bounds__(256) void sgemm_bias(
    const float* __restrict__ Ain, const float* __restrict__ Wm,
    const float* __restrict__ b1, const float* __restrict__ b2,
    int K)
{
    __shared__ float As[8][128];
    __shared__ float Ws[8][128];

    const float* A = FROM_RES ? (const float*)g_res : Ain;
    float* C = g_xp;

    const int tid = threadIdx.x;
    const int bm = blockIdx.x, bn = blockIdx.y;
    const int row = tid >> 1;
    const int kq = (tid & 1) * 4;
    const float* Ag = A + (size_t)(bm * 128 + row) * K + kq;
    const float* Wg = Wm + (size_t)(bn * 128 + row) * K + kq;
    const int tx = tid & 15, ty = tid >> 4;
    const int m0 = ty * 8, n0 = tx * 8;

    u64t acc[8][4];
#pragma unroll
    for (int i = 0; i < 8; i++)
#pragma unroll
        for (int j = 0; j < 4; j++) acc[i][j] = 0ull;

    float4 ap = *(const float4*)Ag;
    float4 wp = *(const float4*)Wg;
    const int nk = K >> 3;

    for (int kt = 0; kt < nk; kt++) {
        As[kq + 0][row] = ap.x; As[kq + 1][row] = ap.y;
        As[kq + 2][row] = ap.z; As[kq + 3][row] = ap.w;
        Ws[kq + 0][row] = wp.x; Ws[kq + 1][row] = wp.y;
        Ws[kq + 2][row] = wp.z; Ws[kq + 3][row] = wp.w;
        __syncthreads();
        if (kt + 1 < nk) {  // prefetch next tile into regs while computing
            ap = *(const float4*)(Ag + (size_t)(kt + 1) * 8);
            wp = *(const float4*)(Wg + (size_t)(kt + 1) * 8);
        }
#pragma unroll
        for (int k = 0; k < 8; k++) {
            float4 a0 = *(const float4*)&As[k][m0];
            float4 a1 = *(const float4*)&As[k][m0 + 4];
            const u64t* bp = (const u64t*)&Ws[k][n0];
            u64t bv0 = bp[0], bv1 = bp[1], bv2 = bp[2], bv3 = bp[3];
            float av[8] = {a0.x, a0.y, a0.z, a0.w, a1.x, a1.y, a1.z, a1.w};
#pragma unroll
            for (int i = 0; i < 8; i++) {
                u64t ai = pk2(av[i], av[i]);
                acc[i][0] = fma2(ai, bv0, acc[i][0]);
                acc[i][1] = fma2(ai, bv1, acc[i][1]);
                acc[i][2] = fma2(ai, bv2, acc[i][2]);
                acc[i][3] = fma2(ai, bv3, acc[i][3]);
            }
        }
        __syncthreads();
    }

    const int gn = bn * 128 + n0;
    float bs[8];
#pragma unroll
    for (int j = 0; j < 8; j++) bs[j] = b1[gn + j] + b2[gn + j];
#pragma unroll
    for (int i = 0; i < 8; i++) {
        float* cp = C + (size_t)(bm * 128 + m0 + i) * Hn + gn;
        float2 p0 = upk(acc[i][0]), p1 = upk(acc[i][1]);
        float2 p2 = upk(acc[i][2]), p3 = upk(acc[i][3]);
        float4 o0 = make_float4(p0.x + bs[0], p0.y + bs[1], p1.x + bs[2], p1.y + bs[3]);
        float4 o1 = make_float4(p2.x + bs[4], p2.y + bs[5], p3.x + bs[6], p3.y + bs[7]);
        *(float4*)cp = o0;
        *(float4*)(cp + 4) = o1;
    }
}

// ---------------- recurrence ----------------------------------------------------
// Grid: 128 CTAs = 16 batch-groups (4 batches each) x 8 column slices (64 cols).
// 512 threads: j = tid&63 (column in slice), kg = tid>>6 (64-wide K chunk).
// Each thread holds its W_hh row-chunk (64 floats = 32 f32x2) in REGISTERS for
// the whole 2048-step loop. Per step: f32x2 dot vs broadcast SMEM h, SMEM
// reduction over kg, tanh, then L2 flag-based exchange among the 8 slice-CTAs.
template <bool STORE_ALL>
__global__ __launch_bounds__(512, 1) void recur_kernel(
    const float* __restrict__ Whh, const float* __restrict__ h0)
{
    __shared__ float sh_h[4 * Hn];   // [batch][k]
    __shared__ float part[4 * Hn];   // [batch][kg*64 + j]

    const int tid = threadIdx.x;
    const int slice = blockIdx.x & 7;
    const int group = blockIdx.x >> 3;
    const int b0 = group * 4;
    const int j = tid & 63;
    const int kg = tid >> 6;
    const int col = slice * 64 + j;

    // Load this thread's W_hh chunk into registers (once).
    u64t w2[32];
    {
        const ulonglong2* wp = (const ulonglong2*)(Whh + (size_t)col * Hn + kg * 64);
#pragma unroll
        for (int i = 0; i < 16; i++) {
            ulonglong2 v = wp[i];
            w2[2 * i] = v.x;
            w2[2 * i + 1] = v.y;
        }
    }
    // Initial hidden state: broadcast h0 to all 4 batches.
#pragma unroll
    for (int bb = 0; bb < 4; bb++) sh_h[bb * Hn + tid] = h0[tid];

    // xp streaming (threads 0..255 own one (batch, column) output each)
    float xpv = 0.f;
    size_t xbase = 0;
    if (tid < 256) {
        xbase = ((size_t)(b0 + (tid >> 6)) * Tn) * Hn + (size_t)(slice * 64 + (tid & 63));
        xpv = __ldg(g_xp + xbase);  // t = 0
    }
    __syncthreads();

    unsigned int* myflag = &g_flags[group][slice];

#pragma unroll 1
    for (int t = 0; t < Tn; t++) {
        // ---- partial dot products: part[b][kg,j] = sum_{k in kg-chunk} W[col,k]*h[b,k]
#pragma unroll
        for (int bb = 0; bb < 4; bb++) {
            const ulonglong2* hp = (const ulonglong2*)(sh_h + bb * Hn + kg * 64);
            u64t a0 = 0ull, a1 = 0ull, a2 = 0ull, a3 = 0ull;
#pragma unroll
            for (int i = 0; i < 8; i++) {
                ulonglong2 v0 = hp[2 * i];
                ulonglong2 v1 = hp[2 * i + 1];
                a0 = fma2(w2[4 * i + 0], v0.x, a0);
                a1 = fma2(w2[4 * i + 1], v0.y, a1);
                a2 = fma2(w2[4 * i + 2], v1.x, a2);
                a3 = fma2(w2[4 * i + 3], v1.y, a3);
            }
            float2 f0 = upk(a0), f1 = upk(a1), f2 = upk(a2), f3 = upk(a3);
            part[bb * Hn + kg * 64 + j] =
                ((f0.x + f0.y) + (f1.x + f1.y)) + ((f2.x + f2.y) + (f3.x + f3.y));
        }
        __syncthreads();

        // ---- reduce over kg, add xp, tanh, publish
        if (tid < 256) {
            const int bb = tid >> 6, jj = tid & 63;
            float s = xpv;
#pragma unroll
            for (int kk = 0; kk < 8; kk++) s += part[bb * Hn + kk * 64 + jj];
            float hnew = tanhf(s);
            __stcg(&g_hbuf[t & 1][(b0 + bb) * Hn + slice * 64 + jj], hnew);
            if (STORE_ALL) {
                g_res[((size_t)(b0 + bb) * Tn + t) * Hn + slice * 64 + jj] = hnew;
            } else if (t == Tn - 1) {
                g_hT[(b0 + bb) * Hn + slice * 64 + jj] = hnew;
            }
            // prefetch next step's xp (hides L2/DRAM latency behind the exchange)
            xpv = (t + 1 < Tn) ? __ldg(g_xp + xbase + (size_t)(t + 1) * Hn) : 0.f;
        }

        if (t + 1 < Tn) {
            __threadfence();
            __syncthreads();
            if (tid == 0) atomicExch(myflag, (unsigned int)(t + 1));
            if (tid < 8) {
                while (atomicAdd(&g_flags[group][tid], 0u) < (unsigned int)(t + 1)) {}
            }
            __syncthreads();
            // reload full [4,512] hidden state for this group (L2, bypass L1)
            {
                const float4* src = (const float4*)&g_hbuf[t & 1][b0 * Hn];
                float4 v = __ldcg(src + tid);  // 512 threads x float4 = 2048 floats
                ((float4*)sh_h)[tid] = v;
            }
            __syncthreads();
        }
    }
}

// ---------------- final FC: out[b,o] = hT[b,:] . W_fc[o,:] + b_fc[o] ------------
__global__ __launch_bounds__(128) void fc_kernel(
    const float* __restrict__ Wfc, const float* __restrict__ bfc,
    float* __restrict__ out)
{
    __shared__ float hs[Hn];
    const int b = blockIdx.x, tid = threadIdx.x;
    ((float4*)hs)[tid] = *(const float4*)&g_hT[b * Hn + tid * 4];
    __syncthreads();
    const float4* wr = (const float4*)(Wfc + (size_t)tid * Hn);
    float acc = 0.f;
#pragma unroll 8
    for (int i = 0; i < Hn / 4; i++) {
        float4 w = __ldg(&wr[i]);
        float4 h = ((const float4*)hs)[i];
        acc += w.x * h.x + w.y * h.y + w.z * h.z + w.w * h.w;
    }
    out[b * On + tid] = acc + bfc[tid];
}

// ---------------- launcher ------------------------------------------------------
extern "C" void kernel_launch(void* const* d_in, const int* in_sizes, int n_in,
                              void* d_out, int out_size)
{
    (void)in_sizes; (void)n_in; (void)out_size;
    const float* x     = (const float*)d_in[0];
    const float* W_ih0 = (const float*)d_in[1];
    const float* W_hh0 = (const float*)d_in[2];
    const float* b_ih0 = (const float*)d_in[3];
    const float* b_hh0 = (const float*)d_in[4];
    const float* h0_0  = (const float*)d_in[5];
    const float* W_ih1 = (const float*)d_in[6];
    const float* W_hh1 = (const float*)d_in[7];
    const float* b_ih1 = (const float*)d_in[8];
    const float* b_hh1 = (const float*)d_in[9];
    const float* h0_1  = (const float*)d_in[10];
    const float* W_fc  = (const float*)d_in[11];
    const float* b_fc  = (const float*)d_in[12];
    float* out = (float*)d_out;

    const dim3 ggrid((Bn * Tn) / 128, Hn / 128);

    // Layer 0
    zero_flags_kernel<<<1, 128>>>();
    sgemm_bias<false><<<ggrid, 256>>>(x, W_ih0, b_ih0, b_hh0, Fn);
    recur_kernel<true><<<NGROUP * NSLICE, 512>>>(W_hh0, h0_0);

    // Layer 1
    zero_flags_kernel<<<1, 128>>>();
    sgemm_bias<true><<<ggrid, 256>>>(nullptr, W_ih1, b_ih1, b_hh1, Hn);
    recur_kernel<false><<<NGROUP * NSLICE, 512>>>(W_hh1, h0_1);

    // Head
    fc_kernel<<<Bn, 128>>>(W_fc, b_fc, out);
}

// round 2
// speedup vs baseline: 1.1050x; 1.1050x over previous
#include <cuda_runtime.h>
#include <cstdint>
#include <cstddef>

// Problem dims
#define Bn 64
#define Tn 2048
#define Fn 256
#define Hn 512
#define On 128

// Fused recurrence partition: 8 groups x 8 batches, 16 slices x 32 cols, 128 CTAs
#define NG 8
#define GB 8
#define NS 16
#define SC 32
#define NKG 8
#define KC 64
#define NTHR 256
#define WSTRIDE 516  // padded W_ih1 row stride (floats) -> conflict-free LDS

// ---------------- static device workspaces -------------------------------------
__device__ __align__(128) float g_xp[(size_t)Bn * Tn * Hn];   // 256 MB input proj
__device__ __align__(128) float g_h0buf[NG][GB * Hn];
__device__ __align__(128) float g_h1buf[NG][GB * Hn];
__device__ __align__(128) float g_hT[Bn * Hn];
__device__ unsigned g_flags0[NG][NS];
__device__ unsigned g_flags1[NG][NS];

typedef unsigned long long u64t;

// ---------------- packed fp32x2 helpers ----------------------------------------
__device__ __forceinline__ u64t fma2(u64t a, u64t b, u64t c) {
    u64t d;
    asm("fma.rn.f32x2 %0, %1, %2, %3;" : "=l"(d) : "l"(a), "l"(b), "l"(c));
    return d;
}
__device__ __forceinline__ u64t pk2(float lo, float hi) {
    u64t r;
    asm("mov.b64 %0, {%1, %2};" : "=l"(r) : "f"(lo), "f"(hi));
    return r;
}
__device__ __forceinline__ float2 upk(u64t v) {
    float2 f;
    asm("mov.b64 {%0, %1}, %2;" : "=f"(f.x), "=f"(f.y) : "l"(v));
    return f;
}
__device__ __forceinline__ unsigned ld_acq(const unsigned* p) {
    unsigned v;
    asm volatile("ld.global.acquire.gpu.u32 %0, [%1];" : "=r"(v) : "l"(p));
    return v;
}

// ---------------- GEMM1: g_xp[M,512] = x[M,256] * W_ih0[512,256]^T + b ----------
// BM=128, BN=128, BK=8, 256 threads, 8x8 microtile in f32x2.
// Block (0,0) also resets the recurrence flags for this replay.
__global__ __launch_bounds__(256) void sgemm_xp(
    const float* __restrict__ A, const float* __restrict__ Wm,
    const float* __restrict__ b1, const float* __restrict__ b2)
{
    __shared__ float As[8][128];
    __shared__ float Ws[8][128];

    const int tid = threadIdx.x;
    if (blockIdx.x == 0 && blockIdx.y == 0 && tid < NG * NS) {
        ((unsigned*)g_flags0)[tid] = 0u;
        ((unsigned*)g_flags1)[tid] = 0u;
    }

    const int K = Fn;
    const int bm = blockIdx.x, bn = blockIdx.y;
    const int row = tid >> 1;
    const int kq = (tid & 1) * 4;
    const float* Ag = A + (size_t)(bm * 128 + row) * K + kq;
    const float* Wg = Wm + (size_t)(bn * 128 + row) * K + kq;
    const int tx = tid & 15, ty = tid >> 4;
    const int m0 = ty * 8, n0 = tx * 8;

    u64t acc[8][4];
#pragma unroll
    for (int i = 0; i < 8; i++)
#pragma unroll
        for (int j = 0; j < 4; j++) acc[i][j] = 0ull;

    float4 ap = *(const float4*)Ag;
    float4 wp = *(const float4*)Wg;
    const int nk = K >> 3;

    for (int kt = 0; kt < nk; kt++) {
        As[kq + 0][row] = ap.x; As[kq + 1][row] = ap.y;
        As[kq + 2][row] = ap.z; As[kq + 3][row] = ap.w;
        Ws[kq + 0][row] = wp.x; Ws[kq + 1][row] = wp.y;
        Ws[kq + 2][row] = wp.z; Ws[kq + 3][row] = wp.w;
        __syncthreads();
        if (kt + 1 < nk) {
            ap = *(const float4*)(Ag + (size_t)(kt + 1) * 8);
            wp = *(const float4*)(Wg + (size_t)(kt + 1) * 8);
        }
#pragma unroll
        for (int k = 0; k < 8; k++) {
            float4 a0 = *(const float4*)&As[k][m0];
            float4 a1 = *(const float4*)&As[k][m0 + 4];
            const u64t* bp = (const u64t*)&Ws[k][n0];
            u64t bv0 = bp[0], bv1 = bp[1], bv2 = bp[2], bv3 = bp[3];
            float av[8] = {a0.x, a0.y, a0.z, a0.w, a1.x, a1.y, a1.z, a1.w};
#pragma unroll
            for (int i = 0; i < 8; i++) {
                u64t ai = pk2(av[i], av[i]);
                acc[i][0] = fma2(ai, bv0, acc[i][0]);
                acc[i][1] = fma2(ai, bv1, acc[i][1]);
                acc[i][2] = fma2(ai, bv2, acc[i][2]);
                acc[i][3] = fma2(ai, bv3, acc[i][3]);
            }
        }
        __syncthreads();
    }

    const int gn = bn * 128 + n0;
    float bs[8];
#pragma unroll
    for (int j = 0; j < 8; j++) bs[j] = b1[gn + j] + b2[gn + j];
#pragma unroll
    for (int i = 0; i < 8; i++) {
        float* cp = g_xp + (size_t)(bm * 128 + m0 + i) * Hn + gn;
        float2 p0 = upk(acc[i][0]), p1 = upk(acc[i][1]);
        float2 p2 = upk(acc[i][2]), p3 = upk(acc[i][3]);
        *(float4*)cp       = make_float4(p0.x + bs[0], p0.y + bs[1], p1.x + bs[2], p1.y + bs[3]);
        *(float4*)(cp + 4) = make_float4(p2.x + bs[4], p2.y + bs[5], p3.x + bs[6], p3.y + bs[7]);
    }
}

// ---------------- fused two-layer pipelined recurrence --------------------------
// 128 CTAs = 8 groups (8 batches) x 16 slices (32 cols). 256 threads:
// j = tid&31 (col in slice), kg = tid>>5 (64-wide K chunk).
// Per step: mv0 = W_hh0.h0 (regs) -> tanh -> publish h0 -> [wait h1 exch, hidden]
// mvB = W_hh1.h1 (regs) -> [wait h0 exch, hidden] -> mvC = W_ih1.h0new (SMEM)
// -> tanh -> publish h1. Cross-CTA exchange via L2 + monotonic acq/rel flags.
__global__ __launch_bounds__(NTHR, 1) void fused_rnn(
    const float* __restrict__ Whh0, const float* __restrict__ Wih1,
    const float* __restrict__ Whh1,
    const float* __restrict__ bih1, const float* __restrict__ bhh1,
    const float* __restrict__ h00, const float* __restrict__ h01)
{
    extern __shared__ float sm[];
    float* wih1 = sm;                         // SC * WSTRIDE = 16512 floats
    float* shh0 = sm + SC * WSTRIDE;          // GB*Hn = 4096
    float* shh1 = shh0 + GB * Hn;             // 4096
    float* part = shh1 + GB * Hn;             // NKG*GB*SC = 2048

    const int tid = threadIdx.x;
    const int slice = blockIdx.x & (NS - 1);
    const int group = blockIdx.x >> 4;
    const int j = tid & 31;
    const int kg = tid >> 5;
    const int col = slice * SC + j;
    const int kb = kg * KC;

    // recurrence weights into registers (64 floats per matrix per thread)
    u64t w0[32], w1[32];
    {
        const ulonglong2* p0 = (const ulonglong2*)(Whh0 + (size_t)col * Hn + kb);
        const ulonglong2* p1 = (const ulonglong2*)(Whh1 + (size_t)col * Hn + kb);
#pragma unroll
        for (int i = 0; i < 16; i++) {
            ulonglong2 a = p0[i]; w0[2 * i] = a.x; w0[2 * i + 1] = a.y;
            ulonglong2 b = p1[i]; w1[2 * i] = b.x; w1[2 * i + 1] = b.y;
        }
    }
    // W_ih1 slice into padded SMEM
    for (int idx = tid; idx < SC * Hn; idx += NTHR) {
        int r = idx >> 9, k = idx & 511;
        wih1[r * WSTRIDE + k] = Wih1[(size_t)(slice * SC + r) * Hn + k];
    }
    // initial hidden states (broadcast to all batches)
    for (int idx = tid; idx < GB * Hn; idx += NTHR) {
        shh0[idx] = h00[idx & 511];
        shh1[idx] = h01[idx & 511];
    }

    // reduce/publish role: thread tid -> (batch rb, col rj)
    const int rb = tid >> 5, rj = tid & 31;
    const int rcol = slice * SC + rj;
    const float bias1 = bih1[rcol] + bhh1[rcol];
    const size_t xbase = ((size_t)(group * GB + rb) * Tn) * Hn + rcol;
    float xpv = __ldg(g_xp + xbase);  // t = 0
    unsigned* f0 = &g_flags0[group][0];
    unsigned* f1 = &g_flags1[group][0];
    float* h0b = g_h0buf[group];
    float* h1b = g_h1buf[group];
    __syncthreads();

    u64t acc[8];

#pragma unroll 1
    for (int t = 0; t < Tn; t++) {
        // ---------- mv0 = W_hh0 . h0_{t-1}
#pragma unroll
        for (int b = 0; b < 8; b++) acc[b] = 0ull;
#pragma unroll
        for (int ii = 0; ii < 16; ii++) {
#pragma unroll
            for (int b = 0; b < 8; b++) {
                ulonglong2 h2 = *(const ulonglong2*)(shh0 + b * Hn + kb + ii * 4);
                acc[b] = fma2(w0[2 * ii],     h2.x, acc[b]);
                acc[b] = fma2(w0[2 * ii + 1], h2.y, acc[b]);
            }
        }
#pragma unroll
        for (int b = 0; b < 8; b++) {
            float2 f = upk(acc[b]);
            part[kg * 256 + b * 32 + j] = f.x + f.y;
        }
        __syncthreads();
        // reduce + tanh + publish h0_t
        {
            float s = xpv;
#pragma unroll
            for (int kk = 0; kk < 8; kk++) s += part[kk * 256 + tid];
            float hn = tanhf(s);
            __stcg(&h0b[rb * Hn + rcol], hn);
            __threadfence();
        }
        __syncthreads();
        if (tid == 0) atomicExch(&f0[slice], (unsigned)(t + 1));
        // prefetch next xp (covered by the rest of the step)
        if (t + 1 < Tn) xpv = __ldg(g_xp + xbase + (size_t)(t + 1) * Hn);

        // ---------- exchange h1_{t-1} (published at end of iter t-1)
        if (t > 0) {
            if (tid < NS) { while (ld_acq(&f1[tid]) < (unsigned)t) {} }
            __syncthreads();
#pragma unroll
            for (int i = 0; i < 4; i++)
                ((float4*)shh1)[i * NTHR + tid] = __ldcg(((const float4*)h1b) + i * NTHR + tid);
            __syncthreads();
        }

        // ---------- mvB = W_hh1 . h1_{t-1} (hides h0 exchange skew)
#pragma unroll
        for (int b = 0; b < 8; b++) acc[b] = 0ull;
#pragma unroll
        for (int ii = 0; ii < 16; ii++) {
#pragma unroll
            for (int b = 0; b < 8; b++) {
                ulonglong2 h2 = *(const ulonglong2*)(shh1 + b * Hn + kb + ii * 4);
                acc[b] = fma2(w1[2 * ii],     h2.x, acc[b]);
                acc[b] = fma2(w1[2 * ii + 1], h2.y, acc[b]);
            }
        }

        // ---------- exchange h0_t
        if (tid < NS) { while (ld_acq(&f0[tid]) < (unsigned)(t + 1)) {} }
        __syncthreads();
#pragma unroll
        for (int i = 0; i < 4; i++)
            ((float4*)shh0)[i * NTHR + tid] = __ldcg(((const float4*)h0b) + i * NTHR + tid);
        __syncthreads();

        // ---------- mvC = W_ih1 . h0_t, accumulated on top of mvB
        {
            const float* wr = wih1 + j * WSTRIDE + kb;
#pragma unroll
            for (int ii = 0; ii < 16; ii++) {
                ulonglong2 w2 = *(const ulonglong2*)(wr + ii * 4);
#pragma unroll
                for (int b = 0; b < 8; b++) {
                    ulonglong2 h2 = *(const ulonglong2*)(shh0 + b * Hn + kb + ii * 4);
                    acc[b] = fma2(w2.x, h2.x, acc[b]);
                    acc[b] = fma2(w2.y, h2.y, acc[b]);
                }
            }
        }
#pragma unroll
        for (int b = 0; b < 8; b++) {
            float2 f = upk(acc[b]);
            part[kg * 256 + b * 32 + j] = f.x + f.y;
        }
        __syncthreads();
        // reduce + tanh -> h1_t
        {
            float s = bias1;
#pragma unroll
            for (int kk = 0; kk < 8; kk++) s += part[kk * 256 + tid];
            float hn = tanhf(s);
            if (t + 1 < Tn) {
                __stcg(&h1b[rb * Hn + rcol], hn);
                __threadfence();
            } else {
                g_hT[(group * GB + rb) * Hn + rcol] = hn;
            }
        }
        __syncthreads();
        if (t + 1 < Tn && tid == 0) atomicExch(&f1[slice], (unsigned)(t + 1));
    }
}

// ---------------- final FC: out[b,o] = hT[b,:] . W_fc[o,:] + b_fc[o] ------------
__global__ __launch_bounds__(128) void fc_kernel(
    const float* __restrict__ Wfc, const float* __restrict__ bfc,
    float* __restrict__ out)
{
    __shared__ float hs[Hn];
    const int b = blockIdx.x, tid = threadIdx.x;
    ((float4*)hs)[tid] = *(const float4*)&g_hT[b * Hn + tid * 4];
    __syncthreads();
    const float4* wr = (const float4*)(Wfc + (size_t)tid * Hn);
    float acc = 0.f;
#pragma unroll 8
    for (int i = 0; i < Hn / 4; i++) {
        float4 w = __ldg(&wr[i]);
        float4 h = ((const float4*)hs)[i];
        acc += w.x * h.x + w.y * h.y + w.z * h.z + w.w * h.w;
    }
    out[b * On + tid] = acc + bfc[tid];
}

// ---------------- launcher ------------------------------------------------------
extern "C" void kernel_launch(void* const* d_in, const int* in_sizes, int n_in,
                              void* d_out, int out_size)
{
    (void)in_sizes; (void)n_in; (void)out_size;
    const float* x     = (const float*)d_in[0];
    const float* W_ih0 = (const float*)d_in[1];
    const float* W_hh0 = (const float*)d_in[2];
    const float* b_ih0 = (const float*)d_in[3];
    const float* b_hh0 = (const float*)d_in[4];
    const float* h0_0  = (const float*)d_in[5];
    const float* W_ih1 = (const float*)d_in[6];
    const float* W_hh1 = (const float*)d_in[7];
    const float* b_ih1 = (const float*)d_in[8];
    const float* b_hh1 = (const float*)d_in[9];
    const float* h0_1  = (const float*)d_in[10];
    const float* W_fc  = (const float*)d_in[11];
    const float* b_fc  = (const float*)d_in[12];
    float* out = (float*)d_out;

    const int fused_smem = (SC * WSTRIDE + 2 * GB * Hn + NKG * GB * SC) * sizeof(float);
    cudaFuncSetAttribute(fused_rnn, cudaFuncAttributeMaxDynamicSharedMemorySize, fused_smem);

    // xp0 = x @ W_ih0^T + b_ih0 + b_hh0  (also resets exchange flags)
    sgemm_xp<<<dim3((Bn * Tn) / 128, Hn / 128), 256>>>(x, W_ih0, b_ih0, b_hh0);

    // fused two-layer recurrence (2048 steps, both layers pipelined)
    fused_rnn<<<NG * NS, NTHR, fused_smem>>>(W_hh0, W_ih1, W_hh1,
                                             b_ih1, b_hh1, h0_0, h0_1);

    // head
    fc_kernel<<<Bn, 128>>>(W_fc, b_fc, out);
}

// round 3
// speedup vs baseline: 1.2227x; 1.1065x over previous
#include <cuda_runtime.h>
#include <cstdint>
#include <cstddef>

// Problem dims
#define Bn 64
#define Tn 2048
#define Fn 256
#define Hn 512
#define On 128

// Fused recurrence partition: 8 groups x 8 batches, 16 slices x 32 cols = 128 CTAs
#define NG 8
#define GB 8
#define NS 16
#define SC 32
#define NKG 16
#define KC 32
#define NTHR 512
#define WSTRIDE 516   // padded W_ih1 row stride (16B-aligned)

// ---------------- static device workspaces -------------------------------------
__device__ __align__(128) float g_xp[(size_t)Bn * Tn * Hn];      // 256 MB input proj
__device__ __align__(128) float g_h0buf[2][NG][GB * Hn];         // parity-buffered h0
__device__ __align__(128) float g_h1buf[2][NG][GB * Hn];         // parity-buffered h1
__device__ __align__(128) float g_hT[Bn * Hn];
__device__ unsigned g_flags0[NG][NS];
__device__ unsigned g_flags1[NG][NS];

typedef unsigned long long u64t;

// ---------------- packed fp32x2 + sync helpers ----------------------------------
__device__ __forceinline__ u64t fma2(u64t a, u64t b, u64t c) {
    u64t d;
    asm("fma.rn.f32x2 %0, %1, %2, %3;" : "=l"(d) : "l"(a), "l"(b), "l"(c));
    return d;
}
__device__ __forceinline__ u64t pk2(float lo, float hi) {
    u64t r;
    asm("mov.b64 %0, {%1, %2};" : "=l"(r) : "f"(lo), "f"(hi));
    return r;
}
__device__ __forceinline__ float2 upk(u64t v) {
    float2 f;
    asm("mov.b64 {%0, %1}, %2;" : "=f"(f.x), "=f"(f.y) : "l"(v));
    return f;
}
__device__ __forceinline__ unsigned ld_acq(const unsigned* p) {
    unsigned v;
    asm volatile("ld.global.acquire.gpu.u32 %0, [%1];" : "=r"(v) : "l"(p));
    return v;
}
__device__ __forceinline__ void st_rel(unsigned* p, unsigned v) {
    asm volatile("st.global.release.gpu.u32 [%0], %1;" :: "l"(p), "r"(v) : "memory");
}
__device__ __forceinline__ unsigned smem_u32(const void* p) {
    unsigned a;
    asm("{ .reg .u64 t; cvta.to.shared.u64 t, %1; cvt.u32.u64 %0, t; }" : "=r"(a) : "l"(p));
    return a;
}
__device__ __forceinline__ void mbar_init(unsigned m, unsigned cnt) {
    asm volatile("mbarrier.init.shared.b64 [%0], %1;" :: "r"(m), "r"(cnt) : "memory");
}
__device__ __forceinline__ void mbar_expect_tx(unsigned m, unsigned bytes) {
    asm volatile("mbarrier.arrive.expect_tx.shared.b64 _, [%0], %1;" :: "r"(m), "r"(bytes) : "memory");
}
__device__ __forceinline__ void bulk_g2s(unsigned dst, const void* src, unsigned bytes, unsigned m) {
    asm volatile("cp.async.bulk.shared::cluster.global.mbarrier::complete_tx::bytes [%0], [%1], %2, [%3];"
                 :: "r"(dst), "l"(src), "r"(bytes), "r"(m) : "memory");
}
__device__ __forceinline__ void mbar_wait(unsigned m, int phase) {
    asm volatile(
        "{\n\t.reg .pred P;\n"
        "WL%=:\n\t"
        "mbarrier.try_wait.parity.acquire.cta.shared::cta.b64 P, [%0], %1, 0x989680;\n\t"
        "@P bra WD%=;\n\t"
        "bra WL%=;\n"
        "WD%=:\n\t}"
        :: "r"(m), "r"((unsigned)phase) : "memory");
}

// ---------------- GEMM1: g_xp[M,512] = x[M,256] * W_ih0[512,256]^T + b ----------
__global__ __launch_bounds__(256) void sgemm_xp(
    const float* __restrict__ A, const float* __restrict__ Wm,
    const float* __restrict__ b1, const float* __restrict__ b2)
{
    __shared__ float As[8][128];
    __shared__ float Ws[8][128];

    const int tid = threadIdx.x;
    if (blockIdx.x == 0 && blockIdx.y == 0 && tid < NG * NS) {
        ((unsigned*)g_flags0)[tid] = 0u;
        ((unsigned*)g_flags1)[tid] = 0u;
    }

    const int K = Fn;
    const int bm = blockIdx.x, bn = blockIdx.y;
    const int row = tid >> 1;
    const int kq = (tid & 1) * 4;
    const float* Ag = A + (size_t)(bm * 128 + row) * K + kq;
    const float* Wg = Wm + (size_t)(bn * 128 + row) * K + kq;
    const int tx = tid & 15, ty = tid >> 4;
    const int m0 = ty * 8, n0 = tx * 8;

    u64t acc[8][4];
#pragma unroll
    for (int i = 0; i < 8; i++)
#pragma unroll
        for (int j = 0; j < 4; j++) acc[i][j] = 0ull;

    float4 ap = *(const float4*)Ag;
    float4 wp = *(const float4*)Wg;
    const int nk = K >> 3;

    for (int kt = 0; kt < nk; kt++) {
        As[kq + 0][row] = ap.x; As[kq + 1][row] = ap.y;
        As[kq + 2][row] = ap.z; As[kq + 3][row] = ap.w;
        Ws[kq + 0][row] = wp.x; Ws[kq + 1][row] = wp.y;
        Ws[kq + 2][row] = wp.z; Ws[kq + 3][row] = wp.w;
        __syncthreads();
        if (kt + 1 < nk) {
            ap = *(const float4*)(Ag + (size_t)(kt + 1) * 8);
            wp = *(const float4*)(Wg + (size_t)(kt + 1) * 8);
        }
#pragma unroll
        for (int k = 0; k < 8; k++) {
            float4 a0 = *(const float4*)&As[k][m0];
            float4 a1 = *(const float4*)&As[k][m0 + 4];
            const u64t* bp = (const u64t*)&Ws[k][n0];
            u64t bv0 = bp[0], bv1 = bp[1], bv2 = bp[2], bv3 = bp[3];
            float av[8] = {a0.x, a0.y, a0.z, a0.w, a1.x, a1.y, a1.z, a1.w};
#pragma unroll
            for (int i = 0; i < 8; i++) {
                u64t ai = pk2(av[i], av[i]);
                acc[i][0] = fma2(ai, bv0, acc[i][0]);
                acc[i][1] = fma2(ai, bv1, acc[i][1]);
                acc[i][2] = fma2(ai, bv2, acc[i][2]);
                acc[i][3] = fma2(ai, bv3, acc[i][3]);
            }
        }
        __syncthreads();
    }

    const int gn = bn * 128 + n0;
    float bs[8];
#pragma unroll
    for (int j = 0; j < 8; j++) bs[j] = b1[gn + j] + b2[gn + j];
#pragma unroll
    for (int i = 0; i < 8; i++) {
        float* cp = g_xp + (size_t)(bm * 128 + m0 + i) * Hn + gn;
        float2 p0 = upk(acc[i][0]), p1 = upk(acc[i][1]);
        float2 p2 = upk(acc[i][2]), p3 = upk(acc[i][3]);
        *(float4*)cp       = make_float4(p0.x + bs[0], p0.y + bs[1], p1.x + bs[2], p1.y + bs[3]);
        *(float4*)(cp + 4) = make_float4(p2.x + bs[4], p2.y + bs[5], p3.x + bs[6], p3.y + bs[7]);
    }
}

// ---------------- fused, layer-1-skewed two-layer recurrence --------------------
// Iteration t computes h0_t AND h1_{t-1}; both need only values exchanged during
// iteration t-1, so all cross-CTA latency hides behind compute.
__global__ __launch_bounds__(NTHR, 1) void fused_rnn(
    const float* __restrict__ Whh0, const float* __restrict__ Wih1,
    const float* __restrict__ Whh1,
    const float* __restrict__ bih1, const float* __restrict__ bhh1,
    const float* __restrict__ h00, const float* __restrict__ h01)
{
    extern __shared__ float sm[];
    float* wih1  = sm;                 // SC*WSTRIDE = 16512 floats
    float* shh0  = sm + SC * WSTRIDE;  // 2 x 4096 (parity)
    float* shh1  = shh0 + 2 * GB * Hn; // 2 x 4096 (parity)
    float* part0 = shh1 + 2 * GB * Hn; // NKG*256 = 4096
    float* part1 = part0 + NKG * 256;  // 4096
    __shared__ __align__(8) unsigned long long mbar[2];

    const int tid = threadIdx.x;
    const int slice = blockIdx.x & (NS - 1);
    const int group = blockIdx.x >> 4;
    const int j = tid & 31;
    const int kg = tid >> 5;
    const int col = slice * SC + j;
    const int kb = kg * KC;

    // recurrence weights into registers (32 floats per matrix per thread)
    u64t w0[16], w1[16];
    {
        const ulonglong2* p0 = (const ulonglong2*)(Whh0 + (size_t)col * Hn + kb);
        const ulonglong2* p1 = (const ulonglong2*)(Whh1 + (size_t)col * Hn + kb);
#pragma unroll
        for (int i = 0; i < 8; i++) {
            ulonglong2 a = p0[i]; w0[2 * i] = a.x; w0[2 * i + 1] = a.y;
            ulonglong2 b = p1[i]; w1[2 * i] = b.x; w1[2 * i + 1] = b.y;
        }
    }
    // W_ih1 slice into padded SMEM
    for (int idx = tid; idx < SC * Hn; idx += NTHR) {
        int r = idx >> 9, k = idx & 511;
        wih1[r * WSTRIDE + k] = Wih1[(size_t)(slice * SC + r) * Hn + k];
    }
    // preload: parity0 of shh0 = h00 (iter 0 input); parity1 of shh1 = h01 (iter 1's h1_{-1})
    for (int idx = tid; idx < GB * Hn; idx += NTHR) {
        shh0[idx] = h00[idx & 511];
        shh1[GB * Hn + idx] = h01[idx & 511];
    }

    const unsigned mb0 = smem_u32(&mbar[0]);
    const unsigned mb1 = smem_u32(&mbar[1]);
    const unsigned sh0a = smem_u32(shh0);
    const unsigned sh1a = smem_u32(shh1);
    const unsigned HBYTES = GB * Hn * 4;  // 16384
    if (tid == 0) {
        mbar_init(mb0, 1);
        mbar_init(mb1, 1);
        asm volatile("fence.proxy.async.shared::cta;" ::: "memory");
    }

    // reduce/publish role: thread tid<256 -> (batch rb, col rj)
    const int rb = tid >> 5, rj = tid & 31;          // valid for tid<256
    const int rcol = slice * SC + rj;
    const float bias1 = bih1[rcol] + bhh1[rcol];
    const size_t xbase = ((size_t)(group * GB + rb) * Tn) * Hn + rcol;
    float xpv = (tid < 256) ? __ldg(g_xp + xbase) : 0.f;
    unsigned* f0 = &g_flags0[group][0];
    unsigned* f1 = &g_flags1[group][0];
    __syncthreads();

    int ph0 = 0, ph1 = 0;
    u64t acc[8];

#pragma unroll 1
    for (int t = 0; t <= Tn; t++) {
        const int cur = t & 1, nxt = cur ^ 1;
        const float* h0c = shh0 + cur * (GB * Hn);
        const float* h1c = shh1 + cur * (GB * Hn);

        // shh0[cur] = h0_{t-1}: wait for the bulk copy issued last iteration
        if (t > 0) { mbar_wait(mb0, ph0); ph0 ^= 1; }

        if (t < Tn) {
            // ---- mv0 = W_hh0 . h0_{t-1}
#pragma unroll
            for (int b = 0; b < 8; b++) acc[b] = 0ull;
#pragma unroll
            for (int ii = 0; ii < 8; ii++) {
#pragma unroll
                for (int b = 0; b < 8; b++) {
                    ulonglong2 h2 = *(const ulonglong2*)(h0c + b * Hn + kb + ii * 4);
                    acc[b] = fma2(w0[2 * ii],     h2.x, acc[b]);
                    acc[b] = fma2(w0[2 * ii + 1], h2.y, acc[b]);
                }
            }
#pragma unroll
            for (int b = 0; b < 8; b++) {
                float2 f = upk(acc[b]);
                part0[kg * 256 + b * 32 + j] = f.x + f.y;
            }
            __syncthreads();
            if (tid < 256) {
                float s0 = xpv, s1 = 0.f;
#pragma unroll
                for (int kk = 0; kk < 16; kk += 2) {
                    s0 += part0[kk * 256 + tid];
                    s1 += part0[(kk + 1) * 256 + tid];
                }
                float hn = tanhf(s0 + s1);
                __stcg(&g_h0buf[cur][group][rb * Hn + rcol], hn);
                if (t + 1 < Tn) xpv = __ldg(g_xp + xbase + (size_t)(t + 1) * Hn);
            }
            __syncthreads();
            if (tid == 0) st_rel(&f0[slice], (unsigned)(t + 1));
        }

        if (t > 0) {
            // shh1[cur] = h1_{t-2} (preloaded for t==1, bulk-copied for t>=2)
            if (t >= 2) { mbar_wait(mb1, ph1); ph1 ^= 1; }

            // ---- mvB = W_hh1 . h1_{t-2}
#pragma unroll
            for (int b = 0; b < 8; b++) acc[b] = 0ull;
#pragma unroll
            for (int ii = 0; ii < 8; ii++) {
#pragma unroll
                for (int b = 0; b < 8; b++) {
                    ulonglong2 h2 = *(const ulonglong2*)(h1c + b * Hn + kb + ii * 4);
                    acc[b] = fma2(w1[2 * ii],     h2.x, acc[b]);
                    acc[b] = fma2(w1[2 * ii + 1], h2.y, acc[b]);
                }
            }

            // ---- kick h0_t -> shh0[nxt] bulk copy (hidden under mvC)
            if (t < Tn && tid < 32) {
                if (tid < 16) { while (ld_acq(&f0[tid]) < (unsigned)(t + 1)) {} }
                __syncwarp();
                if (tid == 0) {
                    mbar_expect_tx(mb0, HBYTES);
                    bulk_g2s(sh0a + nxt * HBYTES, &g_h0buf[cur][group][0], HBYTES, mb0);
                }
            }

            // ---- mvC = W_ih1 . h0_{t-1}, accumulated on top of mvB
            {
                const float* wr = wih1 + j * WSTRIDE + kb;
#pragma unroll
                for (int ii = 0; ii < 8; ii++) {
                    ulonglong2 w2 = *(const ulonglong2*)(wr + ii * 4);
#pragma unroll
                    for (int b = 0; b < 8; b++) {
                        ulonglong2 h2 = *(const ulonglong2*)(h0c + b * Hn + kb + ii * 4);
                        acc[b] = fma2(w2.x, h2.x, acc[b]);
                        acc[b] = fma2(w2.y, h2.y, acc[b]);
                    }
                }
            }
#pragma unroll
            for (int b = 0; b < 8; b++) {
                float2 f = upk(acc[b]);
                part1[kg * 256 + b * 32 + j] = f.x + f.y;
            }
            __syncthreads();
            if (tid < 256) {
                float s0 = bias1, s1 = 0.f;
#pragma unroll
                for (int kk = 0; kk < 16; kk += 2) {
                    s0 += part1[kk * 256 + tid];
                    s1 += part1[(kk + 1) * 256 + tid];
                }
                float hn = tanhf(s0 + s1);
                if (t < Tn) __stcg(&g_h1buf[cur][group][rb * Hn + rcol], hn);
                else        g_hT[(group * GB + rb) * Hn + rcol] = hn;
            }
            __syncthreads();
            if (t < Tn) {
                if (tid == 0) st_rel(&f1[slice], (unsigned)t);
                // kick h1_{t-1} -> shh1[nxt] copy; consumed after next iter's mv0
                if (tid < 32) {
                    if (tid < 16) { while (ld_acq(&f1[tid]) < (unsigned)t) {} }
                    __syncwarp();
                    if (tid == 0) {
                        mbar_expect_tx(mb1, HBYTES);
                        bulk_g2s(sh1a + nxt * HBYTES, &g_h1buf[cur][group][0], HBYTES, mb1);
                    }
                }
            }
        } else {
            // t == 0: kick the very first h0 copy
            if (tid < 32) {
                if (tid < 16) { while (ld_acq(&f0[tid]) < 1u) {} }
                __syncwarp();
                if (tid == 0) {
                    mbar_expect_tx(mb0, HBYTES);
                    bulk_g2s(sh0a + HBYTES, &g_h0buf[0][group][0], HBYTES, mb0);
                }
            }
        }
    }
}

// ---------------- final FC ------------------------------------------------------
__global__ __launch_bounds__(128) void fc_kernel(
    const float* __restrict__ Wfc, const float* __restrict__ bfc,
    float* __restrict__ out)
{
    __shared__ float hs[Hn];
    const int b = blockIdx.x, tid = threadIdx.x;
    ((float4*)hs)[tid] = *(const float4*)&g_hT[b * Hn + tid * 4];
    __syncthreads();
    const float4* wr = (const float4*)(Wfc + (size_t)tid * Hn);
    float acc = 0.f;
#pragma unroll 8
    for (int i = 0; i < Hn / 4; i++) {
        float4 w = __ldg(&wr[i]);
        float4 h = ((const float4*)hs)[i];
        acc += w.x * h.x + w.y * h.y + w.z * h.z + w.w * h.w;
    }
    out[b * On + tid] = acc + bfc[tid];
}

// ---------------- launcher ------------------------------------------------------
extern "C" void kernel_launch(void* const* d_in, const int* in_sizes, int n_in,
                              void* d_out, int out_size)
{
    (void)in_sizes; (void)n_in; (void)out_size;
    const float* x     = (const float*)d_in[0];
    const float* W_ih0 = (const float*)d_in[1];
    const float* W_hh0 = (const float*)d_in[2];
    const float* b_ih0 = (const float*)d_in[3];
    const float* b_hh0 = (const float*)d_in[4];
    const float* h0_0  = (const float*)d_in[5];
    const float* W_ih1 = (const float*)d_in[6];
    const float* W_hh1 = (const float*)d_in[7];
    const float* b_ih1 = (const float*)d_in[8];
    const float* b_hh1 = (const float*)d_in[9];
    const float* h0_1  = (const float*)d_in[10];
    const float* W_fc  = (const float*)d_in[11];
    const float* b_fc  = (const float*)d_in[12];
    float* out = (float*)d_out;

    const int fused_smem =
        (SC * WSTRIDE + 4 * GB * Hn + 2 * NKG * 256) * sizeof(float);
    cudaFuncSetAttribute(fused_rnn, cudaFuncAttributeMaxDynamicSharedMemorySize, fused_smem);

    // xp0 = x @ W_ih0^T + b_ih0 + b_hh0  (block 0 also resets exchange flags)
    sgemm_xp<<<dim3((Bn * Tn) / 128, Hn / 128), 256>>>(x, W_ih0, b_ih0, b_hh0);

    // fused skewed two-layer recurrence
    fused_rnn<<<NG * NS, NTHR, fused_smem>>>(W_hh0, W_ih1, W_hh1,
                                             b_ih1, b_hh1, h0_0, h0_1);

    // head
    fc_kernel<<<Bn, 128>>>(W_fc, b_fc, out);
}